// round 14
// baseline (speedup 1.0000x reference)
#include <cuda_runtime.h>
#include <cuda_bf16.h>
#include <cstdint>

// Transformer block, fully tensor-core (mma.sync m16n8k16 bf16).
// One warp = 32 tokens (4 items) in two 16-row halves; weight B-fragments
// loaded once per pair. R14: X is held in registers as hi/lo bf16x2 pairs
// (hi = the QKV A-fragments themselves, lo = bf16(X - hi), 16 extra regs
// instead of 32 fp32) and reconstructed to fp32 at the proj phase:
// X ~= f32(hi) + f32(lo), error ~2^-17. This fits the 85-reg cap of
// 6 CTAs x 128 thr (24 warps/SM) with no gmem re-read.

// smem word offsets (uint32 words)
#define QKVF 0        // [12 nt][32 lane][4 w] = 1536 words
#define PF   1536     // [4][32][4]  = 512
#define F1F  2048     // [16][32][4] = 2048
#define F2F  4096     // [4 nt][4 grp][32][4] = 2048
#define SMEM_WORDS 6144   // 24 KB

static __device__ __forceinline__ uint32_t cvt_bf2(float lo, float hi) {
    uint32_t r;
    asm("cvt.rn.bf16x2.f32 %0, %1, %2;" : "=r"(r) : "f"(hi), "f"(lo));
    return r;
}
static __device__ __forceinline__ uint32_t prmt(uint32_t a, uint32_t b, uint32_t sel) {
    uint32_t r;
    asm("prmt.b32 %0, %1, %2, %3;" : "=r"(r) : "r"(a), "r"(b), "r"(sel));
    return r;
}
static __device__ __forceinline__ float ex2(float x) {
    float y;
    asm("ex2.approx.ftz.f32 %0, %1;" : "=f"(y) : "f"(x));
    return y;
}
// unpack bf16x2 word: element 0 (low 16 bits) / element 1 (high 16 bits)
static __device__ __forceinline__ float lo16f(uint32_t w) {
    return __uint_as_float(w << 16);
}
static __device__ __forceinline__ float hi16f(uint32_t w) {
    return __uint_as_float(w & 0xffff0000u);
}
static __device__ __forceinline__ void mma16816(float& d0, float& d1, float& d2, float& d3,
                                                uint32_t a0, uint32_t a1, uint32_t a2, uint32_t a3,
                                                uint32_t b0, uint32_t b1) {
    asm volatile("mma.sync.aligned.m16n8k16.row.col.f32.bf16.bf16.f32 "
                 "{%0,%1,%2,%3}, {%4,%5,%6,%7}, {%8,%9}, {%0,%1,%2,%3};"
                 : "+f"(d0), "+f"(d1), "+f"(d2), "+f"(d3)
                 : "r"(a0), "r"(a1), "r"(a2), "r"(a3), "r"(b0), "r"(b1));
}

__global__ void __launch_bounds__(128, 6)
block_mma11(const float* __restrict__ Xg, const float* __restrict__ Wattn,
            const float* __restrict__ Wproj, const float* __restrict__ Wff1,
            const float* __restrict__ Wff2, float* __restrict__ Out, int nwt)
{
    extern __shared__ uint32_t wsm[];
    const int tid = threadIdx.x;

    // Q weights absorb scale * log2(e): S comes out in exp2 domain.
    const float QS = 0.17677669529663687f * 1.4426950408889634f;

    // ---- stage weights in fragment-packed order ----
    // phi k-mapping for QKV/FF1: word w, lane t covers k {4t+2(w&1)+16(w>>1), +1}
    for (int i = tid; i < 1536; i += 128) {             // QKV (n = h*24+d, K|Q|V)
        int w = i & 3, lane = (i >> 2) & 31, nt = i >> 7;
        int g = lane >> 2, t = lane & 3;
        int n = 8 * nt + g;
        int k0 = 4 * t + 2 * (w & 1) + 16 * (w >> 1);
        int h = n / 24, d = n - 24 * h;
        float f0 = Wattn[h * 768 + k0 * 24 + d];
        float f1 = Wattn[h * 768 + (k0 + 1) * 24 + d];
        if (d >= 8 && d < 16) { f0 *= QS; f1 *= QS; }   // Q columns pre-scaled
        wsm[QKVF + i] = cvt_bf2(f0, f1);
    }
    // proj: standard k (O frags standard), phi n-mapping
    for (int i = tid; i < 512; i += 128) {
        int w = i & 3, lane = (i >> 2) & 31, nt = i >> 7;
        int g = lane >> 2, t = lane & 3;
        int k0 = 8 * w + 2 * t;
        int na = 4 * (g >> 1) + 2 * (nt & 1) + (g & 1) + 16 * (nt >> 1);
        wsm[PF + i] = cvt_bf2(Wproj[k0 * 32 + na], Wproj[(k0 + 1) * 32 + na]);
    }
    // ff1: phi k-mapping (A = Y in phi layout), standard n
    for (int i = tid; i < 2048; i += 128) {
        int w = i & 3, lane = (i >> 2) & 31, nt = i >> 7;
        int g = lane >> 2, t = lane & 3;
        int n = 8 * nt + g;
        int k0 = 4 * t + 2 * (w & 1) + 16 * (w >> 1);
        wsm[F1F + i] = cvt_bf2(Wff1[k0 * 128 + n], Wff1[(k0 + 1) * 128 + n]);
    }
    // ff2: standard grouped k (H standard), phi n-mapping; [nt][grp][lane][w]
    for (int i = tid; i < 2048; i += 128) {
        int w = i & 3, lane = (i >> 2) & 31, grp = (i >> 7) & 3, nt = i >> 9;
        int g = lane >> 2, t = lane & 3;
        int k0 = 16 * (2 * grp + (w >> 1)) + 2 * t + 8 * (w & 1);
        int na = 4 * (g >> 1) + 2 * (nt & 1) + (g & 1) + 16 * (nt >> 1);
        wsm[F2F + i] = cvt_bf2(Wff2[k0 * 32 + na], Wff2[(k0 + 1) * 32 + na]);
    }
    __syncthreads();

    const int warp = tid >> 5, lane = tid & 31;
    const int g = lane >> 2, t = lane & 3;
    const uint32_t psel = (g & 1) ? 0x7632u : 0x5410u;
    const int src0 = 8 * t + (g >> 1);
    const bool v0 = (2 * t     <= g);
    const bool v1 = (2 * t + 1 <= g);
    const uint32_t Z = 0;

    const int np = nwt >> 1;                     // 32-token pairs
    const int gw = (blockIdx.x << 2) + warp;
    const int stride = gridDim.x << 2;

    for (int p = gw; p < np; p += stride) {
        const float* Xi = Xg + (size_t)p * 1024;
        float* Og = Out + (size_t)p * 1024;

        // ---- X -> hi (A-frags) + lo (residual correction), all bf16x2 ----
        uint32_t ax[2][4], bxr[2][4];     // hi: rows g / g+8
        uint32_t lax[2][4], lbx[2][4];    // lo: rows g / g+8
        #pragma unroll
        for (int hf = 0; hf < 2; hf++) {
            const float* Xb = Xi + hf * 512;
            float4 a0 = *(const float4*)(Xb + g * 32 + 4 * t);
            float4 a1 = *(const float4*)(Xb + g * 32 + 16 + 4 * t);
            float4 b0 = *(const float4*)(Xb + (g + 8) * 32 + 4 * t);
            float4 b1 = *(const float4*)(Xb + (g + 8) * 32 + 16 + 4 * t);
            ax[hf][0]  = cvt_bf2(a0.x, a0.y);  ax[hf][1]  = cvt_bf2(a0.z, a0.w);
            ax[hf][2]  = cvt_bf2(a1.x, a1.y);  ax[hf][3]  = cvt_bf2(a1.z, a1.w);
            bxr[hf][0] = cvt_bf2(b0.x, b0.y);  bxr[hf][1] = cvt_bf2(b0.z, b0.w);
            bxr[hf][2] = cvt_bf2(b1.x, b1.y);  bxr[hf][3] = cvt_bf2(b1.z, b1.w);
            lax[hf][0] = cvt_bf2(a0.x - lo16f(ax[hf][0]), a0.y - hi16f(ax[hf][0]));
            lax[hf][1] = cvt_bf2(a0.z - lo16f(ax[hf][1]), a0.w - hi16f(ax[hf][1]));
            lax[hf][2] = cvt_bf2(a1.x - lo16f(ax[hf][2]), a1.y - hi16f(ax[hf][2]));
            lax[hf][3] = cvt_bf2(a1.z - lo16f(ax[hf][3]), a1.w - hi16f(ax[hf][3]));
            lbx[hf][0] = cvt_bf2(b0.x - lo16f(bxr[hf][0]), b0.y - hi16f(bxr[hf][0]));
            lbx[hf][1] = cvt_bf2(b0.z - lo16f(bxr[hf][1]), b0.w - hi16f(bxr[hf][1]));
            lbx[hf][2] = cvt_bf2(b1.x - lo16f(bxr[hf][2]), b1.y - hi16f(bxr[hf][2]));
            lbx[hf][3] = cvt_bf2(b1.z - lo16f(bxr[hf][3]), b1.w - hi16f(bxr[hf][3]));
        }

        // ---- QKV + attention per head; halves share B frags ----
        uint32_t o01[2][4], o23[2][4];
        #pragma unroll
        for (int h = 0; h < 4; h++) {
            uint4 Bk = *(const uint4*)(wsm + QKVF + ((3 * h    ) * 32 + lane) * 4);
            uint4 Bq = *(const uint4*)(wsm + QKVF + ((3 * h + 1) * 32 + lane) * 4);
            uint4 Bv = *(const uint4*)(wsm + QKVF + ((3 * h + 2) * 32 + lane) * 4);
            #pragma unroll
            for (int hf = 0; hf < 2; hf++) {
                float kd0=0,kd1=0,kd2=0,kd3=0, qd0=0,qd1=0,qd2=0,qd3=0, vd0=0,vd1=0,vd2=0,vd3=0;
                mma16816(kd0,kd1,kd2,kd3, ax[hf][0],bxr[hf][0],ax[hf][1],bxr[hf][1], Bk.x,Bk.y);
                mma16816(kd0,kd1,kd2,kd3, ax[hf][2],bxr[hf][2],ax[hf][3],bxr[hf][3], Bk.z,Bk.w);
                mma16816(qd0,qd1,qd2,qd3, ax[hf][0],bxr[hf][0],ax[hf][1],bxr[hf][1], Bq.x,Bq.y);
                mma16816(qd0,qd1,qd2,qd3, ax[hf][2],bxr[hf][2],ax[hf][3],bxr[hf][3], Bq.z,Bq.w);
                mma16816(vd0,vd1,vd2,vd3, ax[hf][0],bxr[hf][0],ax[hf][1],bxr[hf][1], Bv.x,Bv.y);
                mma16816(vd0,vd1,vd2,vd3, ax[hf][2],bxr[hf][2],ax[hf][3],bxr[hf][3], Bv.z,Bv.w);

                // S = Q K^T, exp2 domain (2 items packed via k-slots)
                uint32_t bk0 = cvt_bf2(kd0, kd1), bk1 = cvt_bf2(kd2, kd3);
                uint32_t aq0 = cvt_bf2(qd0, qd1), aq3 = cvt_bf2(qd2, qd3);
                float s0=0,s1=0,s2=0,s3=0;
                mma16816(s0,s1,s2,s3, aq0, Z, Z, aq3, bk0, bk1);

                // no-max softmax numerator (|s| << 1 always)
                float p0 = v0 ? ex2(s0) : 0.f;
                float p1 = v1 ? ex2(s1) : 0.f;
                float p2 = v0 ? ex2(s2) : 0.f;
                float p3 = v1 ? ex2(s3) : 0.f;
                uint32_t aP0 = cvt_bf2(p0, p1);
                uint32_t aP3 = cvt_bf2(p2, p3);

                // V^T fragments via shuffle + prmt
                uint32_t pv01 = cvt_bf2(vd0, vd1), pv23 = cvt_bf2(vd2, vd3);
                uint32_t u0 = __shfl_sync(0xffffffffu, pv01, src0);
                uint32_t u1 = __shfl_sync(0xffffffffu, pv01, src0 + 4);
                uint32_t bv0 = prmt(u0, u1, psel);
                uint32_t w0 = __shfl_sync(0xffffffffu, pv23, src0);
                uint32_t w1 = __shfl_sync(0xffffffffu, pv23, src0 + 4);
                uint32_t bv1 = prmt(w0, w1, psel);

                // O_unnorm = P V; sum-reduction overlaps the mma
                float od0=0,od1=0,od2=0,od3=0;
                mma16816(od0,od1,od2,od3, aP0, Z, Z, aP3, bv0, bv1);

                float r0 = p0 + p1;
                r0 += __shfl_xor_sync(0xffffffffu, r0, 1);
                r0 += __shfl_xor_sync(0xffffffffu, r0, 2);
                float i0 = __fdividef(1.f, r0);
                float r1 = p2 + p3;
                r1 += __shfl_xor_sync(0xffffffffu, r1, 1);
                r1 += __shfl_xor_sync(0xffffffffu, r1, 2);
                float i1 = __fdividef(1.f, r1);

                o01[hf][h] = cvt_bf2(od0 * i0, od1 * i0);
                o23[hf][h] = cvt_bf2(od2 * i1, od3 * i1);
            }
        }

        // ---- reconstruct X fp32 from hi+lo into Yf; proj: Yf += O @ Wproj ----
        float Yf[2][4][4];
        #pragma unroll
        for (int hf = 0; hf < 2; hf++) {
            #pragma unroll
            for (int j = 0; j < 4; j++) {
                Yf[hf][j][0] = lo16f(ax[hf][j])  + lo16f(lax[hf][j]);
                Yf[hf][j][1] = hi16f(ax[hf][j])  + hi16f(lax[hf][j]);
                Yf[hf][j][2] = lo16f(bxr[hf][j]) + lo16f(lbx[hf][j]);
                Yf[hf][j][3] = hi16f(bxr[hf][j]) + hi16f(lbx[hf][j]);
            }
        }
        uint32_t ya[2][4], yb[2][4];
        #pragma unroll
        for (int nt = 0; nt < 4; nt++) {
            uint4 Bp = *(const uint4*)(wsm + PF + (nt * 32 + lane) * 4);
            #pragma unroll
            for (int hf = 0; hf < 2; hf++) {
                mma16816(Yf[hf][nt][0], Yf[hf][nt][1], Yf[hf][nt][2], Yf[hf][nt][3],
                         o01[hf][0],o23[hf][0],o01[hf][1],o23[hf][1], Bp.x,Bp.y);
                mma16816(Yf[hf][nt][0], Yf[hf][nt][1], Yf[hf][nt][2], Yf[hf][nt][3],
                         o01[hf][2],o23[hf][2],o01[hf][3],o23[hf][3], Bp.z,Bp.w);
                ya[hf][nt] = cvt_bf2(Yf[hf][nt][0], Yf[hf][nt][1]);
                yb[hf][nt] = cvt_bf2(Yf[hf][nt][2], Yf[hf][nt][3]);
            }
        }

        // ---- FF chunked by K-group: FF1 (4 nts) then FF2 partial; Yf += ----
        #pragma unroll
        for (int grp = 0; grp < 4; grp++) {
            uint32_t hgq[2][4], hhq[2][4];
            #pragma unroll
            for (int q = 0; q < 4; q++) {
                int nt = 4 * grp + q;
                uint4 B1 = *(const uint4*)(wsm + F1F + (nt * 32 + lane) * 4);
                #pragma unroll
                for (int hf = 0; hf < 2; hf++) {
                    float d0=0,d1=0,d2=0,d3=0;
                    mma16816(d0,d1,d2,d3, ya[hf][0],yb[hf][0],ya[hf][1],yb[hf][1], B1.x,B1.y);
                    mma16816(d0,d1,d2,d3, ya[hf][2],yb[hf][2],ya[hf][3],yb[hf][3], B1.z,B1.w);
                    hgq[hf][q] = cvt_bf2(fmaxf(d0, 0.f), fmaxf(d1, 0.f));
                    hhq[hf][q] = cvt_bf2(fmaxf(d2, 0.f), fmaxf(d3, 0.f));
                }
            }
            #pragma unroll
            for (int nt = 0; nt < 4; nt++) {
                uint4 B2 = *(const uint4*)(wsm + F2F + ((nt * 4 + grp) * 32 + lane) * 4);
                #pragma unroll
                for (int hf = 0; hf < 2; hf++) {
                    mma16816(Yf[hf][nt][0], Yf[hf][nt][1], Yf[hf][nt][2], Yf[hf][nt][3],
                             hgq[hf][0],hhq[hf][0],hgq[hf][1],hhq[hf][1], B2.x,B2.y);
                    mma16816(Yf[hf][nt][0], Yf[hf][nt][1], Yf[hf][nt][2], Yf[hf][nt][3],
                             hgq[hf][2],hhq[hf][2],hgq[hf][3],hhq[hf][3], B2.z,B2.w);
                }
            }
        }

        // ---- store: per-lane contiguous float4s (phi layout) ----
        #pragma unroll
        for (int hf = 0; hf < 2; hf++) {
            float* Ob = Og + hf * 512;
            float4 s;
            s.x = Yf[hf][0][0]; s.y = Yf[hf][0][1]; s.z = Yf[hf][1][0]; s.w = Yf[hf][1][1];
            *(float4*)(Ob + g * 32 + 4 * t) = s;
            s.x = Yf[hf][2][0]; s.y = Yf[hf][2][1]; s.z = Yf[hf][3][0]; s.w = Yf[hf][3][1];
            *(float4*)(Ob + g * 32 + 16 + 4 * t) = s;
            s.x = Yf[hf][0][2]; s.y = Yf[hf][0][3]; s.z = Yf[hf][1][2]; s.w = Yf[hf][1][3];
            *(float4*)(Ob + (g + 8) * 32 + 4 * t) = s;
            s.x = Yf[hf][2][2]; s.y = Yf[hf][2][3]; s.z = Yf[hf][3][2]; s.w = Yf[hf][3][3];
            *(float4*)(Ob + (g + 8) * 32 + 16 + 4 * t) = s;
        }
    }
}

extern "C" void kernel_launch(void* const* d_in, const int* in_sizes, int n_in,
                              void* d_out, int out_size) {
    const float* X     = (const float*)d_in[0];
    const float* Wattn = (const float*)d_in[1];
    const float* Wproj = (const float*)d_in[2];
    const float* Wff1  = (const float*)d_in[3];
    const float* Wff2  = (const float*)d_in[4];
    float* out = (float*)d_out;

    int nwt = in_sizes[0] / 512;    // 16-token tiles
    int np = nwt >> 1;              // 32-token pairs
    int sms = 148;
    cudaDeviceGetAttribute(&sms, cudaDevAttrMultiProcessorCount, 0);
    int grid = 6 * sms;
    int maxg = (np + 3) / 4;
    if (grid > maxg) grid = maxg;
    if (grid < 1) grid = 1;

    block_mma11<<<grid, 128, SMEM_WORDS * 4>>>(X, Wattn, Wproj, Wff1, Wff2, out, nwt);
    (void)n_in; (void)out_size;
}

// round 15
// speedup vs baseline: 1.5507x; 1.5507x over previous
#include <cuda_runtime.h>
#include <cuda_bf16.h>
#include <cstdint>

// Transformer block, fully tensor-core (mma.sync m16n8k16 bf16).
// One warp = 32 tokens (4 items) in two 16-row halves; weight B-fragments
// loaded once per pair. Single fp32 accumulator Yf carries
// X -> proj(D+=) -> Y -> FF2(D+=) -> out. FF chunked by K-group.
// phi column permutation: all gmem I/O is per-lane float4 (LDG/STG.128).
// R15 = R11 + lane-spread L2 prefetch of next X tile + asm ex2.

// smem word offsets (uint32 words)
#define QKVF 0        // [12 nt][32 lane][4 w] = 1536 words
#define PF   1536     // [4][32][4]  = 512
#define F1F  2048     // [16][32][4] = 2048
#define F2F  4096     // [4 nt][4 grp][32][4] = 2048
#define SMEM_WORDS 6144   // 24 KB

static __device__ __forceinline__ uint32_t cvt_bf2(float lo, float hi) {
    uint32_t r;
    asm("cvt.rn.bf16x2.f32 %0, %1, %2;" : "=r"(r) : "f"(hi), "f"(lo));
    return r;
}
static __device__ __forceinline__ uint32_t prmt(uint32_t a, uint32_t b, uint32_t sel) {
    uint32_t r;
    asm("prmt.b32 %0, %1, %2, %3;" : "=r"(r) : "r"(a), "r"(b), "r"(sel));
    return r;
}
static __device__ __forceinline__ float ex2(float x) {
    float y;
    asm("ex2.approx.ftz.f32 %0, %1;" : "=f"(y) : "f"(x));
    return y;
}
static __device__ __forceinline__ void mma16816(float& d0, float& d1, float& d2, float& d3,
                                                uint32_t a0, uint32_t a1, uint32_t a2, uint32_t a3,
                                                uint32_t b0, uint32_t b1) {
    asm volatile("mma.sync.aligned.m16n8k16.row.col.f32.bf16.bf16.f32 "
                 "{%0,%1,%2,%3}, {%4,%5,%6,%7}, {%8,%9}, {%0,%1,%2,%3};"
                 : "+f"(d0), "+f"(d1), "+f"(d2), "+f"(d3)
                 : "r"(a0), "r"(a1), "r"(a2), "r"(a3), "r"(b0), "r"(b1));
}

__global__ void __launch_bounds__(128, 5)
block_mma12(const float* __restrict__ Xg, const float* __restrict__ Wattn,
            const float* __restrict__ Wproj, const float* __restrict__ Wff1,
            const float* __restrict__ Wff2, float* __restrict__ Out, int nwt)
{
    extern __shared__ uint32_t wsm[];
    const int tid = threadIdx.x;

    // Q weights absorb scale * log2(e): S comes out in exp2 domain.
    const float QS = 0.17677669529663687f * 1.4426950408889634f;

    // ---- stage weights in fragment-packed order ----
    // phi k-mapping for QKV/FF1: word w, lane t covers k {4t+2(w&1)+16(w>>1), +1}
    for (int i = tid; i < 1536; i += 128) {             // QKV (n = h*24+d, K|Q|V)
        int w = i & 3, lane = (i >> 2) & 31, nt = i >> 7;
        int g = lane >> 2, t = lane & 3;
        int n = 8 * nt + g;
        int k0 = 4 * t + 2 * (w & 1) + 16 * (w >> 1);
        int h = n / 24, d = n - 24 * h;
        float f0 = Wattn[h * 768 + k0 * 24 + d];
        float f1 = Wattn[h * 768 + (k0 + 1) * 24 + d];
        if (d >= 8 && d < 16) { f0 *= QS; f1 *= QS; }   // Q columns pre-scaled
        wsm[QKVF + i] = cvt_bf2(f0, f1);
    }
    // proj: standard k (O frags standard), phi n-mapping
    for (int i = tid; i < 512; i += 128) {
        int w = i & 3, lane = (i >> 2) & 31, nt = i >> 7;
        int g = lane >> 2, t = lane & 3;
        int k0 = 8 * w + 2 * t;
        int na = 4 * (g >> 1) + 2 * (nt & 1) + (g & 1) + 16 * (nt >> 1);
        wsm[PF + i] = cvt_bf2(Wproj[k0 * 32 + na], Wproj[(k0 + 1) * 32 + na]);
    }
    // ff1: phi k-mapping (A = Y in phi layout), standard n
    for (int i = tid; i < 2048; i += 128) {
        int w = i & 3, lane = (i >> 2) & 31, nt = i >> 7;
        int g = lane >> 2, t = lane & 3;
        int n = 8 * nt + g;
        int k0 = 4 * t + 2 * (w & 1) + 16 * (w >> 1);
        wsm[F1F + i] = cvt_bf2(Wff1[k0 * 128 + n], Wff1[(k0 + 1) * 128 + n]);
    }
    // ff2: standard grouped k (H standard), phi n-mapping; [nt][grp][lane][w]
    for (int i = tid; i < 2048; i += 128) {
        int w = i & 3, lane = (i >> 2) & 31, grp = (i >> 7) & 3, nt = i >> 9;
        int g = lane >> 2, t = lane & 3;
        int k0 = 16 * (2 * grp + (w >> 1)) + 2 * t + 8 * (w & 1);
        int na = 4 * (g >> 1) + 2 * (nt & 1) + (g & 1) + 16 * (nt >> 1);
        wsm[F2F + i] = cvt_bf2(Wff2[k0 * 32 + na], Wff2[(k0 + 1) * 32 + na]);
    }
    __syncthreads();

    const int warp = tid >> 5, lane = tid & 31;
    const int g = lane >> 2, t = lane & 3;
    const uint32_t psel = (g & 1) ? 0x7632u : 0x5410u;
    const int src0 = 8 * t + (g >> 1);
    const bool v0 = (2 * t     <= g);
    const bool v1 = (2 * t + 1 <= g);
    const uint32_t Z = 0;

    const int np = nwt >> 1;                     // 32-token pairs
    const int gw = (blockIdx.x << 2) + warp;
    const int stride = gridDim.x << 2;

    for (int p = gw; p < np; p += stride) {
        const float* Xi = Xg + (size_t)p * 1024;
        float* Og = Out + (size_t)p * 1024;

        // ---- load X as per-lane float4s (phi layout); Yf = X ----
        float Yf[2][4][4];
        uint32_t ax[2][4], bxr[2][4];
        #pragma unroll
        for (int hf = 0; hf < 2; hf++) {
            const float* Xb = Xi + hf * 512;
            float4 a0 = *(const float4*)(Xb + g * 32 + 4 * t);
            float4 a1 = *(const float4*)(Xb + g * 32 + 16 + 4 * t);
            float4 b0 = *(const float4*)(Xb + (g + 8) * 32 + 4 * t);
            float4 b1 = *(const float4*)(Xb + (g + 8) * 32 + 16 + 4 * t);
            Yf[hf][0][0] = a0.x; Yf[hf][0][1] = a0.y; Yf[hf][0][2] = b0.x; Yf[hf][0][3] = b0.y;
            Yf[hf][1][0] = a0.z; Yf[hf][1][1] = a0.w; Yf[hf][1][2] = b0.z; Yf[hf][1][3] = b0.w;
            Yf[hf][2][0] = a1.x; Yf[hf][2][1] = a1.y; Yf[hf][2][2] = b1.x; Yf[hf][2][3] = b1.y;
            Yf[hf][3][0] = a1.z; Yf[hf][3][1] = a1.w; Yf[hf][3][2] = b1.z; Yf[hf][3][3] = b1.w;
            ax[hf][0]  = cvt_bf2(a0.x, a0.y);  ax[hf][1]  = cvt_bf2(a0.z, a0.w);
            ax[hf][2]  = cvt_bf2(a1.x, a1.y);  ax[hf][3]  = cvt_bf2(a1.z, a1.w);
            bxr[hf][0] = cvt_bf2(b0.x, b0.y);  bxr[hf][1] = cvt_bf2(b0.z, b0.w);
            bxr[hf][2] = cvt_bf2(b1.x, b1.y);  bxr[hf][3] = cvt_bf2(b1.z, b1.w);
        }

        // ---- prefetch next pair's X tile into L2 (lane-spread, 1 instr) ----
        {
            int pn = p + stride;
            if (pn < np) {
                const char* Xn = (const char*)(Xg + (size_t)pn * 1024) + lane * 128;
                asm volatile("prefetch.global.L2 [%0];" :: "l"(Xn));
            }
        }

        // ---- QKV + attention per head; halves share B frags ----
        uint32_t o01[2][4], o23[2][4];
        #pragma unroll
        for (int h = 0; h < 4; h++) {
            uint4 Bk = *(const uint4*)(wsm + QKVF + ((3 * h    ) * 32 + lane) * 4);
            uint4 Bq = *(const uint4*)(wsm + QKVF + ((3 * h + 1) * 32 + lane) * 4);
            uint4 Bv = *(const uint4*)(wsm + QKVF + ((3 * h + 2) * 32 + lane) * 4);
            #pragma unroll
            for (int hf = 0; hf < 2; hf++) {
                float kd0=0,kd1=0,kd2=0,kd3=0, qd0=0,qd1=0,qd2=0,qd3=0, vd0=0,vd1=0,vd2=0,vd3=0;
                mma16816(kd0,kd1,kd2,kd3, ax[hf][0],bxr[hf][0],ax[hf][1],bxr[hf][1], Bk.x,Bk.y);
                mma16816(kd0,kd1,kd2,kd3, ax[hf][2],bxr[hf][2],ax[hf][3],bxr[hf][3], Bk.z,Bk.w);
                mma16816(qd0,qd1,qd2,qd3, ax[hf][0],bxr[hf][0],ax[hf][1],bxr[hf][1], Bq.x,Bq.y);
                mma16816(qd0,qd1,qd2,qd3, ax[hf][2],bxr[hf][2],ax[hf][3],bxr[hf][3], Bq.z,Bq.w);
                mma16816(vd0,vd1,vd2,vd3, ax[hf][0],bxr[hf][0],ax[hf][1],bxr[hf][1], Bv.x,Bv.y);
                mma16816(vd0,vd1,vd2,vd3, ax[hf][2],bxr[hf][2],ax[hf][3],bxr[hf][3], Bv.z,Bv.w);

                // S = Q K^T, exp2 domain (2 items packed via k-slots)
                uint32_t bk0 = cvt_bf2(kd0, kd1), bk1 = cvt_bf2(kd2, kd3);
                uint32_t aq0 = cvt_bf2(qd0, qd1), aq3 = cvt_bf2(qd2, qd3);
                float s0=0,s1=0,s2=0,s3=0;
                mma16816(s0,s1,s2,s3, aq0, Z, Z, aq3, bk0, bk1);

                // no-max softmax numerator (|s| << 1 always)
                float p0 = v0 ? ex2(s0) : 0.f;
                float p1 = v1 ? ex2(s1) : 0.f;
                float p2 = v0 ? ex2(s2) : 0.f;
                float p3 = v1 ? ex2(s3) : 0.f;
                uint32_t aP0 = cvt_bf2(p0, p1);
                uint32_t aP3 = cvt_bf2(p2, p3);

                // V^T fragments via shuffle + prmt
                uint32_t pv01 = cvt_bf2(vd0, vd1), pv23 = cvt_bf2(vd2, vd3);
                uint32_t u0 = __shfl_sync(0xffffffffu, pv01, src0);
                uint32_t u1 = __shfl_sync(0xffffffffu, pv01, src0 + 4);
                uint32_t bv0 = prmt(u0, u1, psel);
                uint32_t w0 = __shfl_sync(0xffffffffu, pv23, src0);
                uint32_t w1 = __shfl_sync(0xffffffffu, pv23, src0 + 4);
                uint32_t bv1 = prmt(w0, w1, psel);

                // O_unnorm = P V; sum-reduction overlaps the mma
                float od0=0,od1=0,od2=0,od3=0;
                mma16816(od0,od1,od2,od3, aP0, Z, Z, aP3, bv0, bv1);

                float r0 = p0 + p1;
                r0 += __shfl_xor_sync(0xffffffffu, r0, 1);
                r0 += __shfl_xor_sync(0xffffffffu, r0, 2);
                float i0 = __fdividef(1.f, r0);
                float r1 = p2 + p3;
                r1 += __shfl_xor_sync(0xffffffffu, r1, 1);
                r1 += __shfl_xor_sync(0xffffffffu, r1, 2);
                float i1 = __fdividef(1.f, r1);

                o01[hf][h] = cvt_bf2(od0 * i0, od1 * i0);
                o23[hf][h] = cvt_bf2(od2 * i1, od3 * i1);
            }
        }

        // ---- proj: Yf += O @ Wproj (phi n-staged) ----
        uint32_t ya[2][4], yb[2][4];
        #pragma unroll
        for (int nt = 0; nt < 4; nt++) {
            uint4 Bp = *(const uint4*)(wsm + PF + (nt * 32 + lane) * 4);
            #pragma unroll
            for (int hf = 0; hf < 2; hf++) {
                mma16816(Yf[hf][nt][0], Yf[hf][nt][1], Yf[hf][nt][2], Yf[hf][nt][3],
                         o01[hf][0],o23[hf][0],o01[hf][1],o23[hf][1], Bp.x,Bp.y);
                mma16816(Yf[hf][nt][0], Yf[hf][nt][1], Yf[hf][nt][2], Yf[hf][nt][3],
                         o01[hf][2],o23[hf][2],o01[hf][3],o23[hf][3], Bp.z,Bp.w);
                ya[hf][nt] = cvt_bf2(Yf[hf][nt][0], Yf[hf][nt][1]);
                yb[hf][nt] = cvt_bf2(Yf[hf][nt][2], Yf[hf][nt][3]);
            }
        }

        // ---- FF chunked by K-group: FF1 (4 nts) then FF2 partial; Yf += ----
        #pragma unroll
        for (int grp = 0; grp < 4; grp++) {
            uint32_t hgq[2][4], hhq[2][4];
            #pragma unroll
            for (int q = 0; q < 4; q++) {
                int nt = 4 * grp + q;
                uint4 B1 = *(const uint4*)(wsm + F1F + (nt * 32 + lane) * 4);
                #pragma unroll
                for (int hf = 0; hf < 2; hf++) {
                    float d0=0,d1=0,d2=0,d3=0;
                    mma16816(d0,d1,d2,d3, ya[hf][0],yb[hf][0],ya[hf][1],yb[hf][1], B1.x,B1.y);
                    mma16816(d0,d1,d2,d3, ya[hf][2],yb[hf][2],ya[hf][3],yb[hf][3], B1.z,B1.w);
                    hgq[hf][q] = cvt_bf2(fmaxf(d0, 0.f), fmaxf(d1, 0.f));
                    hhq[hf][q] = cvt_bf2(fmaxf(d2, 0.f), fmaxf(d3, 0.f));
                }
            }
            #pragma unroll
            for (int nt = 0; nt < 4; nt++) {
                uint4 B2 = *(const uint4*)(wsm + F2F + ((nt * 4 + grp) * 32 + lane) * 4);
                #pragma unroll
                for (int hf = 0; hf < 2; hf++) {
                    mma16816(Yf[hf][nt][0], Yf[hf][nt][1], Yf[hf][nt][2], Yf[hf][nt][3],
                             hgq[hf][0],hhq[hf][0],hgq[hf][1],hhq[hf][1], B2.x,B2.y);
                    mma16816(Yf[hf][nt][0], Yf[hf][nt][1], Yf[hf][nt][2], Yf[hf][nt][3],
                             hgq[hf][2],hhq[hf][2],hgq[hf][3],hhq[hf][3], B2.z,B2.w);
                }
            }
        }

        // ---- store: per-lane contiguous float4s (phi layout) ----
        #pragma unroll
        for (int hf = 0; hf < 2; hf++) {
            float* Ob = Og + hf * 512;
            float4 s;
            s.x = Yf[hf][0][0]; s.y = Yf[hf][0][1]; s.z = Yf[hf][1][0]; s.w = Yf[hf][1][1];
            *(float4*)(Ob + g * 32 + 4 * t) = s;
            s.x = Yf[hf][2][0]; s.y = Yf[hf][2][1]; s.z = Yf[hf][3][0]; s.w = Yf[hf][3][1];
            *(float4*)(Ob + g * 32 + 16 + 4 * t) = s;
            s.x = Yf[hf][0][2]; s.y = Yf[hf][0][3]; s.z = Yf[hf][1][2]; s.w = Yf[hf][1][3];
            *(float4*)(Ob + (g + 8) * 32 + 4 * t) = s;
            s.x = Yf[hf][2][2]; s.y = Yf[hf][2][3]; s.z = Yf[hf][3][2]; s.w = Yf[hf][3][3];
            *(float4*)(Ob + (g + 8) * 32 + 16 + 4 * t) = s;
        }
    }
}

extern "C" void kernel_launch(void* const* d_in, const int* in_sizes, int n_in,
                              void* d_out, int out_size) {
    const float* X     = (const float*)d_in[0];
    const float* Wattn = (const float*)d_in[1];
    const float* Wproj = (const float*)d_in[2];
    const float* Wff1  = (const float*)d_in[3];
    const float* Wff2  = (const float*)d_in[4];
    float* out = (float*)d_out;

    int nwt = in_sizes[0] / 512;    // 16-token tiles
    int np = nwt >> 1;              // 32-token pairs
    int sms = 148;
    cudaDeviceGetAttribute(&sms, cudaDevAttrMultiProcessorCount, 0);
    int grid = 5 * sms;
    int maxg = (np + 3) / 4;
    if (grid > maxg) grid = maxg;
    if (grid < 1) grid = 1;

    block_mma12<<<grid, 128, SMEM_WORDS * 4>>>(X, Wattn, Wproj, Wff1, Wff2, out, nwt);
    (void)n_in; (void)out_size;
}